// round 8
// baseline (speedup 1.0000x reference)
#include <cuda_runtime.h>
#include <cuda_bf16.h>
#include <math.h>
#include <cstdint>

// Problem constants (fixed by the dataset)
#define B    4
#define N    16384
#define C    256
#define C3   768
#define T    64        // categories
#define HDS  8
#define D    32        // head dim
#define GS   128       // group size
#define NG   128      // groups per batch
#define CHUNK 128
#define NCH   128      // N / CHUNK

// ---------------- scratch (static device allocations only) ----------------
__device__ int   g_tkid[B * N];
__device__ int   g_counts[B * T * NCH];     // [b][key][chunk], scanned in place
__device__ int   g_sortidx[B * N];          // sorted position -> original token
__device__ float g_y[(size_t)B * N * C];    // attention output in ORIGINAL token order

// bf16 hi/lo split of a pair of floats, packed as bf16x2 words
__device__ __forceinline__ void split2(float a, float b, uint32_t& hi, uint32_t& lo) {
    __nv_bfloat162 h = __floats2bfloat162_rn(a, b);
    float ra = a - __bfloat162float(h.x);
    float rb = b - __bfloat162float(h.y);
    __nv_bfloat162 l = __floats2bfloat162_rn(ra, rb);
    hi = *(uint32_t*)&h;
    lo = *(uint32_t*)&l;
}

// warp-level bf16 MMA, fp32 accumulate (sm_80+, no arch-feature gate)
__device__ __forceinline__ void mma16816(float* c, const uint32_t* a, const uint32_t* b) {
    asm volatile(
        "mma.sync.aligned.m16n8k16.row.col.f32.bf16.bf16.f32 "
        "{%0,%1,%2,%3}, {%4,%5,%6,%7}, {%8,%9}, {%0,%1,%2,%3};"
        : "+f"(c[0]), "+f"(c[1]), "+f"(c[2]), "+f"(c[3])
        : "r"(a[0]), "r"(a[1]), "r"(a[2]), "r"(a[3]), "r"(b[0]), "r"(b[1]));
}

__device__ __forceinline__ uint32_t smem_u32(const void* p) {
    uint32_t a;
    asm("{ .reg .u64 t; cvta.to.shared.u64 t, %1; cvt.u32.u64 %0, t; }"
        : "=r"(a) : "l"(p));
    return a;
}
__device__ __forceinline__ void ldsm4(uint32_t* r, uint32_t addr) {
    asm volatile("ldmatrix.sync.aligned.m8n8.x4.shared.b16 {%0,%1,%2,%3}, [%4];"
                 : "=r"(r[0]), "=r"(r[1]), "=r"(r[2]), "=r"(r[3]) : "r"(addr));
}

// ---------------- K1: per-token argmax + per-chunk histogram ----------------
__global__ void k_argmax_count(const float* __restrict__ sim) {
    int b = blockIdx.y, ch = blockIdx.x, tid = threadIdx.x;
    __shared__ float ss[CHUNK * T];   // 32 KB
    __shared__ int   hist[T];

    const float4* src = (const float4*)(sim + ((size_t)(b * N + ch * CHUNK)) * T);
    float4* dst = (float4*)ss;
#pragma unroll
    for (int i = tid; i < CHUNK * T / 4; i += CHUNK) dst[i] = src[i];
    if (tid < T) hist[tid] = 0;
    __syncthreads();

    const float* row = ss + tid * T;
    float best = row[0];
    int   bi   = 0;
#pragma unroll
    for (int j = 1; j < T; j++) {
        float v = row[j];
        if (v > best) { best = v; bi = j; }   // first-max == jnp.argmax tie rule
    }
    g_tkid[b * N + ch * CHUNK + tid] = bi;
    atomicAdd(&hist[bi], 1);
    __syncthreads();
    if (tid < T) g_counts[(b * T + tid) * NCH + ch] = hist[tid];
}

// ---------------- K2: per-batch exclusive scan of counts (8192 ints) ----------------
__global__ void k_scan() {
    const int PER = (T * NCH) / 1024;   // 8
    int b = blockIdx.x, tid = threadIdx.x;
    __shared__ int t1[1024], t2[1024];
    int* cnt = g_counts + b * T * NCH;

    int v[PER];
    int s = 0;
#pragma unroll
    for (int i = 0; i < PER; i++) { v[i] = cnt[tid * PER + i]; s += v[i]; }
    t1[tid] = s;
    __syncthreads();

    int* a  = t1;
    int* bb = t2;
    for (int off = 1; off < 1024; off <<= 1) {
        int x = a[tid];
        if (tid >= off) x += a[tid - off];
        bb[tid] = x;
        __syncthreads();
        int* tmp = a; a = bb; bb = tmp;
    }
    int pre = (tid == 0) ? 0 : a[tid - 1];
#pragma unroll
    for (int i = 0; i < PER; i++) { cnt[tid * PER + i] = pre; pre += v[i]; }
}

// ---------------- K3: stable scatter (match_any rank, no serial loop) --------
__global__ void k_scatter() {
    int b = blockIdx.y, ch = blockIdx.x, tid = threadIdx.x;
    __shared__ int wcnt[4][T];
    int w = tid >> 5, lane = tid & 31;
    for (int i = tid; i < 4 * T; i += CHUNK) ((int*)wcnt)[i] = 0;
    __syncthreads();

    int token = ch * CHUNK + tid;
    int key   = g_tkid[b * N + token];
    unsigned mask  = __match_any_sync(0xffffffffu, key);
    int lrank  = __popc(mask & ((1u << lane) - 1));
    int leader = __ffs(mask) - 1;
    if (lane == leader) wcnt[w][key] = __popc(mask);
    __syncthreads();

    int rank = lrank;
#pragma unroll
    for (int ww = 0; ww < 4; ww++)
        if (ww < w) rank += wcnt[ww][key];
    int pos = g_counts[(b * T + key) * NCH + ch] + rank;
    g_sortidx[b * N + pos] = token;
}

// ---------------- K4: grouped attention via warp MMA (bf16 3-term split) -----
// One CTA (256 thr / 8 warps) per (head, group, batch); warp owns 16 q-rows.
// Q,K smem rows padded to 40 bf16 (80 B = 20 words): 8-row ldmatrix phases hit
// banks {0,20,8,28,16,4,24,12}(+3) -> conflict-free.
// V transposed Vt[dim][key], rows 136 bf16 (68 words, 68%32=4) -> conflict-free.
#define ATP 40
#define VTP 136
#define SQH 0
#define SQL (SQH + GS * ATP * 2)          // 10240 each
#define SKH (SQL + GS * ATP * 2)
#define SKL (SKH + GS * ATP * 2)
#define SVH (SKL + GS * ATP * 2)          // Vt: 32*272 = 8704 each
#define SVL (SVH + D * VTP * 2)
#define STOK (SVL + D * VTP * 2)
#define SM_ATTN (STOK + GS * 4)           // 58,880 B

__global__ void __launch_bounds__(256, 2)
k_attn_mma(const float* __restrict__ qkv, const float* __restrict__ logit_scale) {
    extern __shared__ char sm[];
    uint32_t sb = smem_u32(sm);
    int head = blockIdx.x, g = blockIdx.y, b = blockIdx.z;
    int tid = threadIdx.x;
    int* toks = (int*)(sm + STOK);

    int r = tid >> 1, h = tid & 1;           // 2 threads per token row
    int token = g_sortidx[b * N + g * GS + r];
    if (h == 0) toks[r] = token;

    float scale = __expf(fminf(logit_scale[0], 4.6051701859880914f));  // log(100)

    // ---- gather: split q (pre-scaled), k into smem; v transposed ----
    const float4* base =
        (const float4*)(qkv + ((size_t)(b * N) + token) * C3 + head * D);
#pragma unroll
    for (int p = h * 4; p < h * 4 + 4; p += 2) {   // q: 2 float4 pairs
        float4 v0 = base[p], v1 = base[p + 1];
        v0.x *= scale; v0.y *= scale; v0.z *= scale; v0.w *= scale;
        v1.x *= scale; v1.y *= scale; v1.z *= scale; v1.w *= scale;
        uint32_t h0, l0, h1, l1, h2, l2, h3, l3;
        split2(v0.x, v0.y, h0, l0); split2(v0.z, v0.w, h1, l1);
        split2(v1.x, v1.y, h2, l2); split2(v1.z, v1.w, h3, l3);
        *(uint2*)(sm + SQH + r * (ATP * 2) + p * 8)     = make_uint2(h0, h1);
        *(uint2*)(sm + SQH + r * (ATP * 2) + p * 8 + 8) = make_uint2(h2, h3);
        *(uint2*)(sm + SQL + r * (ATP * 2) + p * 8)     = make_uint2(l0, l1);
        *(uint2*)(sm + SQL + r * (ATP * 2) + p * 8 + 8) = make_uint2(l2, l3);
    }
#pragma unroll
    for (int p = h * 4; p < h * 4 + 4; p += 2) {   // k (+256 floats = +64 float4)
        float4 v0 = base[64 + p], v1 = base[64 + p + 1];
        uint32_t h0, l0, h1, l1, h2, l2, h3, l3;
        split2(v0.x, v0.y, h0, l0); split2(v0.z, v0.w, h1, l1);
        split2(v1.x, v1.y, h2, l2); split2(v1.z, v1.w, h3, l3);
        *(uint2*)(sm + SKH + r * (ATP * 2) + p * 8)     = make_uint2(h0, h1);
        *(uint2*)(sm + SKH + r * (ATP * 2) + p * 8 + 8) = make_uint2(h2, h3);
        *(uint2*)(sm + SKL + r * (ATP * 2) + p * 8)     = make_uint2(l0, l1);
        *(uint2*)(sm + SKL + r * (ATP * 2) + p * 8 + 8) = make_uint2(l2, l3);
    }
    {
        __nv_bfloat16* vh = (__nv_bfloat16*)(sm + SVH);
        __nv_bfloat16* vl = (__nv_bfloat16*)(sm + SVL);
#pragma unroll
        for (int p = h * 4; p < h * 4 + 4; p++) {  // v (+512 floats = +128 float4)
            float4 v = base[128 + p];
            uint32_t h0, l0, h1, l1;
            split2(v.x, v.y, h0, l0);
            split2(v.z, v.w, h1, l1);
            __nv_bfloat162 H0 = *(__nv_bfloat162*)&h0, L0 = *(__nv_bfloat162*)&l0;
            __nv_bfloat162 H1 = *(__nv_bfloat162*)&h1, L1 = *(__nv_bfloat162*)&l1;
            int d0 = p * 4;
            vh[(d0 + 0) * VTP + r] = H0.x;  vl[(d0 + 0) * VTP + r] = L0.x;
            vh[(d0 + 1) * VTP + r] = H0.y;  vl[(d0 + 1) * VTP + r] = L0.y;
            vh[(d0 + 2) * VTP + r] = H1.x;  vl[(d0 + 2) * VTP + r] = L1.x;
            vh[(d0 + 3) * VTP + r] = H1.y;  vl[(d0 + 3) * VTP + r] = L1.y;
        }
    }
    __syncthreads();

    int w = tid >> 5, lane = tid & 31;
    int gq = lane >> 2, t = lane & 3;
    int quad = lane >> 3, rrow = lane & 7;   // ldmatrix lane decomposition

    // ---- Q fragments via ldmatrix.x4 (A-operand, 16 rows x k16 per ki) ----
    uint32_t qh[2][4], ql[2][4];
    {
        int qrow = w * 16 + (quad & 1) * 8 + rrow;
#pragma unroll
        for (int ki = 0; ki < 2; ki++) {
            uint32_t off = qrow * 80 + ki * 32 + (quad >> 1) * 16;
            ldsm4(qh[ki], sb + SQH + off);
            ldsm4(ql[ki], sb + SQL + off);
        }
    }

    // ---- S = (scale*Q) K^T, 16x128 per warp in registers ----
    float S[16][4];
#pragma unroll
    for (int ni = 0; ni < 16; ni++)
#pragma unroll
        for (int rr = 0; rr < 4; rr++) S[ni][rr] = 0.f;

#pragma unroll
    for (int np = 0; np < 8; np++) {         // pairs of 8-key B tiles
        int krow = np * 16 + (quad >> 1) * 8 + rrow;
#pragma unroll
        for (int ki = 0; ki < 2; ki++) {
            uint32_t off = krow * 80 + ki * 32 + (quad & 1) * 16;
            uint32_t bh[4], bl[4];
            ldsm4(bh, sb + SKH + off);       // {b0,b1}=ni_even, {b2,b3}=ni_odd
            ldsm4(bl, sb + SKL + off);
            mma16816(S[2 * np],     qh[ki], bh);
            mma16816(S[2 * np],     qh[ki], bl);
            mma16816(S[2 * np],     ql[ki], bh);
            mma16816(S[2 * np + 1], qh[ki], bh + 2);
            mma16816(S[2 * np + 1], qh[ki], bl + 2);
            mma16816(S[2 * np + 1], ql[ki], bh + 2);
        }
    }

    // ---- softmax (two-pass, quad-shuffle row reductions) ----
    float mx0 = -INFINITY, mx1 = -INFINITY;
#pragma unroll
    for (int ni = 0; ni < 16; ni++) {
        mx0 = fmaxf(mx0, fmaxf(S[ni][0], S[ni][1]));
        mx1 = fmaxf(mx1, fmaxf(S[ni][2], S[ni][3]));
    }
#pragma unroll
    for (int x = 1; x <= 2; x <<= 1) {
        mx0 = fmaxf(mx0, __shfl_xor_sync(0xffffffffu, mx0, x));
        mx1 = fmaxf(mx1, __shfl_xor_sync(0xffffffffu, mx1, x));
    }

    float sm0 = 0.f, sm1 = 0.f;
#pragma unroll
    for (int ni = 0; ni < 16; ni++) {
        S[ni][0] = __expf(S[ni][0] - mx0);
        S[ni][1] = __expf(S[ni][1] - mx0);
        S[ni][2] = __expf(S[ni][2] - mx1);
        S[ni][3] = __expf(S[ni][3] - mx1);
        sm0 += S[ni][0] + S[ni][1];
        sm1 += S[ni][2] + S[ni][3];
    }
#pragma unroll
    for (int x = 1; x <= 2; x <<= 1) {
        sm0 += __shfl_xor_sync(0xffffffffu, sm0, x);
        sm1 += __shfl_xor_sync(0xffffffffu, sm1, x);
    }

    // ---- Y = P V  (P fragments assembled from S registers) ----
    float Y[4][4];
#pragma unroll
    for (int nj = 0; nj < 4; nj++)
#pragma unroll
        for (int rr = 0; rr < 4; rr++) Y[nj][rr] = 0.f;

#pragma unroll
    for (int kk = 0; kk < 8; kk++) {
        uint32_t ph[4], pl[4];
        split2(S[2 * kk][0],     S[2 * kk][1],     ph[0], pl[0]);
        split2(S[2 * kk][2],     S[2 * kk][3],     ph[1], pl[1]);
        split2(S[2 * kk + 1][0], S[2 * kk + 1][1], ph[2], pl[2]);
        split2(S[2 * kk + 1][2], S[2 * kk + 1][3], ph[3], pl[3]);
#pragma unroll
        for (int njp = 0; njp < 2; njp++) {
            int vrow = njp * 16 + (quad >> 1) * 8 + rrow;
            uint32_t off = vrow * 272 + kk * 32 + (quad & 1) * 16;
            uint32_t bvh[4], bvl[4];
            ldsm4(bvh, sb + SVH + off);      // {b0,b1}=nj_even, {b2,b3}=nj_odd
            ldsm4(bvl, sb + SVL + off);
            mma16816(Y[2 * njp],     ph, bvh);
            mma16816(Y[2 * njp],     ph, bvl);
            mma16816(Y[2 * njp],     pl, bvh);
            mma16816(Y[2 * njp + 1], ph, bvh + 2);
            mma16816(Y[2 * njp + 1], ph, bvl + 2);
            mma16816(Y[2 * njp + 1], pl, bvh + 2);
        }
    }

    // ---- epilogue: normalize, scatter to ORIGINAL token order ----
    float i0 = 1.0f / sm0, i1 = 1.0f / sm1;
    int row0 = w * 16 + gq;
    float* o0 = g_y + ((size_t)(b * N) + toks[row0]) * C + head * D;
    float* o1 = g_y + ((size_t)(b * N) + toks[row0 + 8]) * C + head * D;
#pragma unroll
    for (int nj = 0; nj < 4; nj++) {
        *(float2*)(o0 + nj * 8 + 2 * t) = make_float2(Y[nj][0] * i0, Y[nj][1] * i0);
        *(float2*)(o1 + nj * 8 + 2 * t) = make_float2(Y[nj][2] * i1, Y[nj][3] * i1);
    }
}

// ---------------- K5: projection GEMM via warp MMA (bf16 3-term split) -------
// Block 128(M) x 128(N), 8 warps (4m x 2n), warp tile 32x64. A re-read only 2x.
#define PM 128
#define PN 128
#define PKC 64
#define PSTR 72                 // bf16 elements per smem row (144 B)
#define SA_HI 0
#define SA_LO (PM * PSTR * 2)
#define SB_HI (SA_LO + PM * PSTR * 2)
#define SB_LO (SB_HI + PN * PSTR * 2)
#define SM_PROJ (SB_LO + PN * PSTR * 2)   // 73728 B

__global__ void __launch_bounds__(256)
k_proj_mma(const float* __restrict__ W, const float* __restrict__ bias,
           float* __restrict__ out) {
    extern __shared__ char sm[];
    int tid = threadIdx.x;
    int wid = tid >> 5, lane = tid & 31;
    int g = lane >> 2, t = lane & 3;
    int wm = wid >> 1, wn = wid & 1;          // 4 x 2 warp grid, tile 32x64
    int m0 = blockIdx.y * PM, n0 = blockIdx.x * PN;

    const uint32_t* Ah = (const uint32_t*)(sm + SA_HI);
    const uint32_t* Al = (const uint32_t*)(sm + SA_LO);
    const uint32_t* Bh = (const uint32_t*)(sm + SB_HI);
    const uint32_t* Bl = (const uint32_t*)(sm + SB_LO);
    const int RS = PSTR / 2;                  // 36 words per row

    float acc[2][8][4];
#pragma unroll
    for (int mi = 0; mi < 2; mi++)
#pragma unroll
        for (int ni = 0; ni < 8; ni++)
#pragma unroll
            for (int r = 0; r < 4; r++) acc[mi][ni][r] = 0.f;

    for (int ch = 0; ch < C / PKC; ch++) {
#pragma unroll 2
        for (int i = tid; i < PM * (PKC / 4); i += 256) {
            int r = i >> 4, c4 = i & 15;
            float4 v = *(const float4*)(g_y + (size_t)(m0 + r) * C + ch * PKC + c4 * 4);
            uint32_t h0, l0, h1, l1;
            split2(v.x, v.y, h0, l0);
            split2(v.z, v.w, h1, l1);
            int off = r * (PSTR * 2) + c4 * 8;
            *(uint2*)(sm + SA_HI + off) = make_uint2(h0, h1);
            *(uint2*)(sm + SA_LO + off) = make_uint2(l0, l1);
        }
#pragma unroll 2
        for (int i = tid; i < PN * (PKC / 4); i += 256) {
            int r = i >> 4, c4 = i & 15;
            float4 v = *(const float4*)(W + (size_t)(n0 + r) * C + ch * PKC + c4 * 4);
            uint32_t h0, l0, h1, l1;
            split2(v.x, v.y, h0, l0);
            split2(v.z, v.w, h1, l1);
            int off = r * (PSTR * 2) + c4 * 8;
            *(uint2*)(sm + SB_HI + off) = make_uint2(h0, h1);
            *(uint2*)(sm + SB_LO + off) = make_uint2(l0, l1);
        }
        __syncthreads();

#pragma unroll
        for (int ksi = 0; ksi < PKC / 16; ksi++) {
            int kw = ksi * 8 + t;

            uint32_t ah[2][4], al[2][4];
#pragma unroll
            for (int mi = 0; mi < 2; mi++) {
                int rb = (wm * 32 + mi * 16 + g) * RS + kw;
                ah[mi][0] = Ah[rb];              al[mi][0] = Al[rb];
                ah[mi][1] = Ah[rb + 8 * RS];     al[mi][1] = Al[rb + 8 * RS];
                ah[mi][2] = Ah[rb + 4];          al[mi][2] = Al[rb + 4];
                ah[mi][3] = Ah[rb + 8 * RS + 4]; al[mi][3] = Al[rb + 8 * RS + 4];
            }
#pragma unroll
            for (int ni = 0; ni < 8; ni++) {
                int rb = (wn * 64 + ni * 8 + g) * RS + kw;
                uint32_t bh[2] = { Bh[rb], Bh[rb + 4] };
                uint32_t bl[2] = { Bl[rb], Bl[rb + 4] };
#pragma unroll
                for (int mi = 0; mi < 2; mi++) {
                    mma16816(acc[mi][ni], ah[mi], bh);   // hh
                    mma16816(acc[mi][ni], ah[mi], bl);   // hl
                    mma16816(acc[mi][ni], al[mi], bh);   // lh
                }
            }
        }
        __syncthreads();
    }

#pragma unroll
    for (int ni = 0; ni < 8; ni++) {
        int cn = n0 + wn * 64 + ni * 8 + t * 2;
        float2 bb = *(const float2*)(bias + cn);
#pragma unroll
        for (int mi = 0; mi < 2; mi++) {
            int r0 = m0 + wm * 32 + mi * 16 + g;
            float2 o0, o1;
            o0.x = acc[mi][ni][0] + bb.x;
            o0.y = acc[mi][ni][1] + bb.y;
            o1.x = acc[mi][ni][2] + bb.x;
            o1.y = acc[mi][ni][3] + bb.y;
            *(float2*)(out + (size_t)r0 * C + cn)       = o0;
            *(float2*)(out + (size_t)(r0 + 8) * C + cn) = o1;
        }
    }
}

// ---------------- launch ----------------
extern "C" void kernel_launch(void* const* d_in, const int* in_sizes, int n_in,
                              void* d_out, int out_size) {
    const float* qkv  = (const float*)d_in[0];
    const float* sim  = (const float*)d_in[1];
    const float* W    = (const float*)d_in[2];
    const float* bias = (const float*)d_in[3];
    const float* ls   = (const float*)d_in[4];
    float* out = (float*)d_out;

    cudaFuncSetAttribute(k_attn_mma, cudaFuncAttributeMaxDynamicSharedMemorySize,
                         SM_ATTN);
    cudaFuncSetAttribute(k_proj_mma, cudaFuncAttributeMaxDynamicSharedMemorySize,
                         SM_PROJ);

    k_argmax_count<<<dim3(NCH, B), CHUNK>>>(sim);
    k_scan<<<B, 1024>>>();
    k_scatter<<<dim3(NCH, B), CHUNK>>>();
    k_attn_mma<<<dim3(HDS, NG, B), 256, SM_ATTN>>>(qkv, ls);
    k_proj_mma<<<dim3(C / PN, (B * N) / PM), 256, SM_PROJ>>>(W, bias, out);
}

// round 9
// speedup vs baseline: 1.2163x; 1.2163x over previous
#include <cuda_runtime.h>
#include <cuda_bf16.h>
#include <math.h>
#include <cstdint>

// Problem constants (fixed by the dataset)
#define B    4
#define N    16384
#define C    256
#define C3   768
#define T    64        // categories
#define HDS  8
#define D    32        // head dim
#define GS   128       // group size
#define NG   128       // groups per batch
#define CHUNK 128
#define NCH   128      // N / CHUNK

// ---------------- scratch (static device allocations only) ----------------
__device__ int   g_tkid[B * N];
__device__ int   g_counts[B * T * NCH];     // [b][key][chunk], scanned in place
__device__ int   g_sortidx[B * N];          // sorted position -> original token
__device__ float g_y[(size_t)B * N * C];    // attention output in ORIGINAL token order

// bf16 hi/lo split of a pair of floats, packed as bf16x2 words
__device__ __forceinline__ void split2(float a, float b, uint32_t& hi, uint32_t& lo) {
    __nv_bfloat162 h = __floats2bfloat162_rn(a, b);
    float ra = a - __bfloat162float(h.x);
    float rb = b - __bfloat162float(h.y);
    __nv_bfloat162 l = __floats2bfloat162_rn(ra, rb);
    hi = *(uint32_t*)&h;
    lo = *(uint32_t*)&l;
}

// warp-level bf16 MMA, fp32 accumulate (sm_80+, no arch-feature gate)
__device__ __forceinline__ void mma16816(float* c, const uint32_t* a, const uint32_t* b) {
    asm volatile(
        "mma.sync.aligned.m16n8k16.row.col.f32.bf16.bf16.f32 "
        "{%0,%1,%2,%3}, {%4,%5,%6,%7}, {%8,%9}, {%0,%1,%2,%3};"
        : "+f"(c[0]), "+f"(c[1]), "+f"(c[2]), "+f"(c[3])
        : "r"(a[0]), "r"(a[1]), "r"(a[2]), "r"(a[3]), "r"(b[0]), "r"(b[1]));
}

__device__ __forceinline__ uint32_t smem_u32(const void* p) {
    uint32_t a;
    asm("{ .reg .u64 t; cvta.to.shared.u64 t, %1; cvt.u32.u64 %0, t; }"
        : "=r"(a) : "l"(p));
    return a;
}
__device__ __forceinline__ void ldsm4(uint32_t* r, uint32_t addr) {
    asm volatile("ldmatrix.sync.aligned.m8n8.x4.shared.b16 {%0,%1,%2,%3}, [%4];"
                 : "=r"(r[0]), "=r"(r[1]), "=r"(r[2]), "=r"(r[3]) : "r"(addr));
}

// ---------------- K1: per-token argmax + per-chunk histogram ----------------
__global__ void k_argmax_count(const float* __restrict__ sim) {
    int b = blockIdx.y, ch = blockIdx.x, tid = threadIdx.x;
    __shared__ float ss[CHUNK * T];   // 32 KB
    __shared__ int   hist[T];

    const float4* src = (const float4*)(sim + ((size_t)(b * N + ch * CHUNK)) * T);
    float4* dst = (float4*)ss;
#pragma unroll
    for (int i = tid; i < CHUNK * T / 4; i += CHUNK) dst[i] = src[i];
    if (tid < T) hist[tid] = 0;
    __syncthreads();

    const float* row = ss + tid * T;
    float best = row[0];
    int   bi   = 0;
#pragma unroll
    for (int j = 1; j < T; j++) {
        float v = row[j];
        if (v > best) { best = v; bi = j; }   // first-max == jnp.argmax tie rule
    }
    g_tkid[b * N + ch * CHUNK + tid] = bi;
    atomicAdd(&hist[bi], 1);
    __syncthreads();
    if (tid < T) g_counts[(b * T + tid) * NCH + ch] = hist[tid];
}

// ---------------- K2: per-batch exclusive scan of counts (8192 ints) ----------------
__global__ void k_scan() {
    const int PER = (T * NCH) / 1024;   // 8
    int b = blockIdx.x, tid = threadIdx.x;
    __shared__ int t1[1024], t2[1024];
    int* cnt = g_counts + b * T * NCH;

    int v[PER];
    int s = 0;
#pragma unroll
    for (int i = 0; i < PER; i++) { v[i] = cnt[tid * PER + i]; s += v[i]; }
    t1[tid] = s;
    __syncthreads();

    int* a  = t1;
    int* bb = t2;
    for (int off = 1; off < 1024; off <<= 1) {
        int x = a[tid];
        if (tid >= off) x += a[tid - off];
        bb[tid] = x;
        __syncthreads();
        int* tmp = a; a = bb; bb = tmp;
    }
    int pre = (tid == 0) ? 0 : a[tid - 1];
#pragma unroll
    for (int i = 0; i < PER; i++) { cnt[tid * PER + i] = pre; pre += v[i]; }
}

// ---------------- K3: stable scatter (match_any rank, no serial loop) --------
__global__ void k_scatter() {
    int b = blockIdx.y, ch = blockIdx.x, tid = threadIdx.x;
    __shared__ int wcnt[4][T];
    int w = tid >> 5, lane = tid & 31;
    for (int i = tid; i < 4 * T; i += CHUNK) ((int*)wcnt)[i] = 0;
    __syncthreads();

    int token = ch * CHUNK + tid;
    int key   = g_tkid[b * N + token];
    unsigned mask  = __match_any_sync(0xffffffffu, key);
    int lrank  = __popc(mask & ((1u << lane) - 1));
    int leader = __ffs(mask) - 1;
    if (lane == leader) wcnt[w][key] = __popc(mask);
    __syncthreads();

    int rank = lrank;
#pragma unroll
    for (int ww = 0; ww < 4; ww++)
        if (ww < w) rank += wcnt[ww][key];
    int pos = g_counts[(b * T + key) * NCH + ch] + rank;
    g_sortidx[b * N + pos] = token;
}

// ---------------- K4: grouped attention via warp MMA (bf16 3-term split) -----
// One CTA (256 thr / 8 warps) per (head, group, batch); warp owns 16 q-rows.
// Q,K smem rows padded to 40 bf16 (80 B = 20 words): 8-row ldmatrix phases hit
// banks {0,20,8,28,16,4,24,12}(+3) -> conflict-free.
// V transposed Vt[dim][key], rows 136 bf16 (68 words, 68%32=4) -> conflict-free.
#define ATP 40
#define VTP 136
#define SQH 0
#define SQL (SQH + GS * ATP * 2)          // 10240 each
#define SKH (SQL + GS * ATP * 2)
#define SKL (SKH + GS * ATP * 2)
#define SVH (SKL + GS * ATP * 2)          // Vt: 32*272 = 8704 each
#define SVL (SVH + D * VTP * 2)
#define STOK (SVL + D * VTP * 2)
#define SM_ATTN (STOK + GS * 4)           // 58,880 B

__global__ void __launch_bounds__(256, 2)
k_attn_mma(const float* __restrict__ qkv, const float* __restrict__ logit_scale) {
    extern __shared__ char sm[];
    uint32_t sb = smem_u32(sm);
    int head = blockIdx.x, g = blockIdx.y, b = blockIdx.z;
    int tid = threadIdx.x;
    int* toks = (int*)(sm + STOK);

    int r = tid >> 1, h = tid & 1;           // 2 threads per token row
    int token = g_sortidx[b * N + g * GS + r];
    if (h == 0) toks[r] = token;

    float scale = __expf(fminf(logit_scale[0], 4.6051701859880914f));  // log(100)

    // ---- gather: split q (pre-scaled), k into smem; v transposed ----
    const float4* base =
        (const float4*)(qkv + ((size_t)(b * N) + token) * C3 + head * D);
#pragma unroll
    for (int p = h * 4; p < h * 4 + 4; p += 2) {   // q: 2 float4 pairs
        float4 v0 = base[p], v1 = base[p + 1];
        v0.x *= scale; v0.y *= scale; v0.z *= scale; v0.w *= scale;
        v1.x *= scale; v1.y *= scale; v1.z *= scale; v1.w *= scale;
        uint32_t h0, l0, h1, l1, h2, l2, h3, l3;
        split2(v0.x, v0.y, h0, l0); split2(v0.z, v0.w, h1, l1);
        split2(v1.x, v1.y, h2, l2); split2(v1.z, v1.w, h3, l3);
        *(uint2*)(sm + SQH + r * (ATP * 2) + p * 8)     = make_uint2(h0, h1);
        *(uint2*)(sm + SQH + r * (ATP * 2) + p * 8 + 8) = make_uint2(h2, h3);
        *(uint2*)(sm + SQL + r * (ATP * 2) + p * 8)     = make_uint2(l0, l1);
        *(uint2*)(sm + SQL + r * (ATP * 2) + p * 8 + 8) = make_uint2(l2, l3);
    }
#pragma unroll
    for (int p = h * 4; p < h * 4 + 4; p += 2) {   // k (+256 floats = +64 float4)
        float4 v0 = base[64 + p], v1 = base[64 + p + 1];
        uint32_t h0, l0, h1, l1, h2, l2, h3, l3;
        split2(v0.x, v0.y, h0, l0); split2(v0.z, v0.w, h1, l1);
        split2(v1.x, v1.y, h2, l2); split2(v1.z, v1.w, h3, l3);
        *(uint2*)(sm + SKH + r * (ATP * 2) + p * 8)     = make_uint2(h0, h1);
        *(uint2*)(sm + SKH + r * (ATP * 2) + p * 8 + 8) = make_uint2(h2, h3);
        *(uint2*)(sm + SKL + r * (ATP * 2) + p * 8)     = make_uint2(l0, l1);
        *(uint2*)(sm + SKL + r * (ATP * 2) + p * 8 + 8) = make_uint2(l2, l3);
    }
    {
        __nv_bfloat16* vh = (__nv_bfloat16*)(sm + SVH);
        __nv_bfloat16* vl = (__nv_bfloat16*)(sm + SVL);
#pragma unroll
        for (int p = h * 4; p < h * 4 + 4; p++) {  // v (+512 floats = +128 float4)
            float4 v = base[128 + p];
            uint32_t h0, l0, h1, l1;
            split2(v.x, v.y, h0, l0);
            split2(v.z, v.w, h1, l1);
            __nv_bfloat162 H0 = *(__nv_bfloat162*)&h0, L0 = *(__nv_bfloat162*)&l0;
            __nv_bfloat162 H1 = *(__nv_bfloat162*)&h1, L1 = *(__nv_bfloat162*)&l1;
            int d0 = p * 4;
            vh[(d0 + 0) * VTP + r] = H0.x;  vl[(d0 + 0) * VTP + r] = L0.x;
            vh[(d0 + 1) * VTP + r] = H0.y;  vl[(d0 + 1) * VTP + r] = L0.y;
            vh[(d0 + 2) * VTP + r] = H1.x;  vl[(d0 + 2) * VTP + r] = L1.x;
            vh[(d0 + 3) * VTP + r] = H1.y;  vl[(d0 + 3) * VTP + r] = L1.y;
        }
    }
    __syncthreads();

    int w = tid >> 5, lane = tid & 31;
    int gq = lane >> 2, t = lane & 3;
    int quad = lane >> 3, rrow = lane & 7;   // ldmatrix lane decomposition

    // ---- Q fragments via ldmatrix.x4 (A-operand, 16 rows x k16 per ki) ----
    uint32_t qh[2][4], ql[2][4];
    {
        int qrow = w * 16 + (quad & 1) * 8 + rrow;
#pragma unroll
        for (int ki = 0; ki < 2; ki++) {
            uint32_t off = qrow * 80 + ki * 32 + (quad >> 1) * 16;
            ldsm4(qh[ki], sb + SQH + off);
            ldsm4(ql[ki], sb + SQL + off);
        }
    }

    // ---- S = (scale*Q) K^T, 16x128 per warp in registers ----
    float S[16][4];
#pragma unroll
    for (int ni = 0; ni < 16; ni++)
#pragma unroll
        for (int rr = 0; rr < 4; rr++) S[ni][rr] = 0.f;

#pragma unroll
    for (int np = 0; np < 8; np++) {         // pairs of 8-key B tiles
        int krow = np * 16 + (quad >> 1) * 8 + rrow;
#pragma unroll
        for (int ki = 0; ki < 2; ki++) {
            uint32_t off = krow * 80 + ki * 32 + (quad & 1) * 16;
            uint32_t bh[4], bl[4];
            ldsm4(bh, sb + SKH + off);       // {b0,b1}=ni_even, {b2,b3}=ni_odd
            ldsm4(bl, sb + SKL + off);
            mma16816(S[2 * np],     qh[ki], bh);
            mma16816(S[2 * np],     qh[ki], bl);
            mma16816(S[2 * np],     ql[ki], bh);
            mma16816(S[2 * np + 1], qh[ki], bh + 2);
            mma16816(S[2 * np + 1], qh[ki], bl + 2);
            mma16816(S[2 * np + 1], ql[ki], bh + 2);
        }
    }

    // ---- softmax (two-pass, quad-shuffle row reductions) ----
    float mx0 = -INFINITY, mx1 = -INFINITY;
#pragma unroll
    for (int ni = 0; ni < 16; ni++) {
        mx0 = fmaxf(mx0, fmaxf(S[ni][0], S[ni][1]));
        mx1 = fmaxf(mx1, fmaxf(S[ni][2], S[ni][3]));
    }
#pragma unroll
    for (int x = 1; x <= 2; x <<= 1) {
        mx0 = fmaxf(mx0, __shfl_xor_sync(0xffffffffu, mx0, x));
        mx1 = fmaxf(mx1, __shfl_xor_sync(0xffffffffu, mx1, x));
    }

    float sm0 = 0.f, sm1 = 0.f;
#pragma unroll
    for (int ni = 0; ni < 16; ni++) {
        S[ni][0] = __expf(S[ni][0] - mx0);
        S[ni][1] = __expf(S[ni][1] - mx0);
        S[ni][2] = __expf(S[ni][2] - mx1);
        S[ni][3] = __expf(S[ni][3] - mx1);
        sm0 += S[ni][0] + S[ni][1];
        sm1 += S[ni][2] + S[ni][3];
    }
#pragma unroll
    for (int x = 1; x <= 2; x <<= 1) {
        sm0 += __shfl_xor_sync(0xffffffffu, sm0, x);
        sm1 += __shfl_xor_sync(0xffffffffu, sm1, x);
    }

    // ---- Y = P V  (P fragments assembled from S registers) ----
    float Y[4][4];
#pragma unroll
    for (int nj = 0; nj < 4; nj++)
#pragma unroll
        for (int rr = 0; rr < 4; rr++) Y[nj][rr] = 0.f;

#pragma unroll
    for (int kk = 0; kk < 8; kk++) {
        uint32_t ph[4], pl[4];
        split2(S[2 * kk][0],     S[2 * kk][1],     ph[0], pl[0]);
        split2(S[2 * kk][2],     S[2 * kk][3],     ph[1], pl[1]);
        split2(S[2 * kk + 1][0], S[2 * kk + 1][1], ph[2], pl[2]);
        split2(S[2 * kk + 1][2], S[2 * kk + 1][3], ph[3], pl[3]);
#pragma unroll
        for (int njp = 0; njp < 2; njp++) {
            int vrow = njp * 16 + (quad >> 1) * 8 + rrow;
            uint32_t off = vrow * 272 + kk * 32 + (quad & 1) * 16;
            uint32_t bvh[4], bvl[4];
            ldsm4(bvh, sb + SVH + off);      // {b0,b1}=nj_even, {b2,b3}=nj_odd
            ldsm4(bvl, sb + SVL + off);
            mma16816(Y[2 * njp],     ph, bvh);
            mma16816(Y[2 * njp],     ph, bvl);
            mma16816(Y[2 * njp],     pl, bvh);
            mma16816(Y[2 * njp + 1], ph, bvh + 2);
            mma16816(Y[2 * njp + 1], ph, bvl + 2);
            mma16816(Y[2 * njp + 1], pl, bvh + 2);
        }
    }

    // ---- epilogue: normalize, scatter to ORIGINAL token order ----
    float i0 = 1.0f / sm0, i1 = 1.0f / sm1;
    int row0 = w * 16 + gq;
    float* o0 = g_y + ((size_t)(b * N) + toks[row0]) * C + head * D;
    float* o1 = g_y + ((size_t)(b * N) + toks[row0 + 8]) * C + head * D;
#pragma unroll
    for (int nj = 0; nj < 4; nj++) {
        *(float2*)(o0 + nj * 8 + 2 * t) = make_float2(Y[nj][0] * i0, Y[nj][1] * i0);
        *(float2*)(o1 + nj * 8 + 2 * t) = make_float2(Y[nj][2] * i1, Y[nj][3] * i1);
    }
}

// ---------------- K5: projection GEMM via warp MMA (bf16 3-term split) -------
// R7-proven config: block 128(M) x 64(N), 8 warps (4m x 2n), warp tile 32x32.
#define PM 128
#define PN 64
#define PKC 64
#define PSTR 72                 // bf16 elements per smem row (144 B)
#define SA_HI 0
#define SA_LO (PM * PSTR * 2)
#define SB_HI (SA_LO + PM * PSTR * 2)
#define SB_LO (SB_HI + PN * PSTR * 2)
#define SM_PROJ (SB_LO + PN * PSTR * 2)   // 55296 B

__global__ void __launch_bounds__(256)
k_proj_mma(const float* __restrict__ W, const float* __restrict__ bias,
           float* __restrict__ out) {
    extern __shared__ char sm[];
    int tid = threadIdx.x;
    int wid = tid >> 5, lane = tid & 31;
    int g = lane >> 2, t = lane & 3;
    int wm = wid >> 1, wn = wid & 1;          // 4 x 2 warp grid
    int m0 = blockIdx.y * PM, n0 = blockIdx.x * PN;

    const uint32_t* Ah = (const uint32_t*)(sm + SA_HI);
    const uint32_t* Al = (const uint32_t*)(sm + SA_LO);
    const uint32_t* Bh = (const uint32_t*)(sm + SB_HI);
    const uint32_t* Bl = (const uint32_t*)(sm + SB_LO);
    const int RS = PSTR / 2;                  // 36 words per row

    float acc[2][4][4];
#pragma unroll
    for (int mi = 0; mi < 2; mi++)
#pragma unroll
        for (int ni = 0; ni < 4; ni++)
#pragma unroll
            for (int r = 0; r < 4; r++) acc[mi][ni][r] = 0.f;

    for (int ch = 0; ch < C / PKC; ch++) {
#pragma unroll 2
        for (int i = tid; i < PM * (PKC / 4); i += 256) {
            int r = i >> 4, c4 = i & 15;
            float4 v = *(const float4*)(g_y + (size_t)(m0 + r) * C + ch * PKC + c4 * 4);
            uint32_t h0, l0, h1, l1;
            split2(v.x, v.y, h0, l0);
            split2(v.z, v.w, h1, l1);
            int off = r * (PSTR * 2) + c4 * 8;
            *(uint2*)(sm + SA_HI + off) = make_uint2(h0, h1);
            *(uint2*)(sm + SA_LO + off) = make_uint2(l0, l1);
        }
#pragma unroll 2
        for (int i = tid; i < PN * (PKC / 4); i += 256) {
            int r = i >> 4, c4 = i & 15;
            float4 v = *(const float4*)(W + (size_t)(n0 + r) * C + ch * PKC + c4 * 4);
            uint32_t h0, l0, h1, l1;
            split2(v.x, v.y, h0, l0);
            split2(v.z, v.w, h1, l1);
            int off = r * (PSTR * 2) + c4 * 8;
            *(uint2*)(sm + SB_HI + off) = make_uint2(h0, h1);
            *(uint2*)(sm + SB_LO + off) = make_uint2(l0, l1);
        }
        __syncthreads();

#pragma unroll
        for (int ksi = 0; ksi < PKC / 16; ksi++) {
            int kw = ksi * 8 + t;

            uint32_t ah[2][4], al[2][4];
#pragma unroll
            for (int mi = 0; mi < 2; mi++) {
                int rb = (wm * 32 + mi * 16 + g) * RS + kw;
                ah[mi][0] = Ah[rb];              al[mi][0] = Al[rb];
                ah[mi][1] = Ah[rb + 8 * RS];     al[mi][1] = Al[rb + 8 * RS];
                ah[mi][2] = Ah[rb + 4];          al[mi][2] = Al[rb + 4];
                ah[mi][3] = Ah[rb + 8 * RS + 4]; al[mi][3] = Al[rb + 8 * RS + 4];
            }
            uint32_t bh[4][2], bl[4][2];
#pragma unroll
            for (int ni = 0; ni < 4; ni++) {
                int rb = (wn * 32 + ni * 8 + g) * RS + kw;
                bh[ni][0] = Bh[rb];     bl[ni][0] = Bl[rb];
                bh[ni][1] = Bh[rb + 4]; bl[ni][1] = Bl[rb + 4];
            }
#pragma unroll
            for (int mi = 0; mi < 2; mi++)
#pragma unroll
                for (int ni = 0; ni < 4; ni++) {
                    mma16816(acc[mi][ni], ah[mi], bh[ni]);   // hh
                    mma16816(acc[mi][ni], ah[mi], bl[ni]);   // hl
                    mma16816(acc[mi][ni], al[mi], bh[ni]);   // lh
                }
        }
        __syncthreads();
    }

#pragma unroll
    for (int ni = 0; ni < 4; ni++) {
        int cn = n0 + wn * 32 + ni * 8 + t * 2;
        float2 bb = *(const float2*)(bias + cn);
#pragma unroll
        for (int mi = 0; mi < 2; mi++) {
            int r0 = m0 + wm * 32 + mi * 16 + g;
            float2 o0, o1;
            o0.x = acc[mi][ni][0] + bb.x;
            o0.y = acc[mi][ni][1] + bb.y;
            o1.x = acc[mi][ni][2] + bb.x;
            o1.y = acc[mi][ni][3] + bb.y;
            *(float2*)(out + (size_t)r0 * C + cn)       = o0;
            *(float2*)(out + (size_t)(r0 + 8) * C + cn) = o1;
        }
    }
}

// ---------------- launch ----------------
extern "C" void kernel_launch(void* const* d_in, const int* in_sizes, int n_in,
                              void* d_out, int out_size) {
    const float* qkv  = (const float*)d_in[0];
    const float* sim  = (const float*)d_in[1];
    const float* W    = (const float*)d_in[2];
    const float* bias = (const float*)d_in[3];
    const float* ls   = (const float*)d_in[4];
    float* out = (float*)d_out;

    cudaFuncSetAttribute(k_attn_mma, cudaFuncAttributeMaxDynamicSharedMemorySize,
                         SM_ATTN);
    cudaFuncSetAttribute(k_proj_mma, cudaFuncAttributeMaxDynamicSharedMemorySize,
                         SM_PROJ);

    k_argmax_count<<<dim3(NCH, B), CHUNK>>>(sim);
    k_scan<<<B, 1024>>>();
    k_scatter<<<dim3(NCH, B), CHUNK>>>();
    k_attn_mma<<<dim3(HDS, NG, B), 256, SM_ATTN>>>(qkv, ls);
    k_proj_mma<<<dim3(C / PN, (B * N) / PM), 256, SM_PROJ>>>(W, bias, out);
}